// round 11
// baseline (speedup 1.0000x reference)
#include <cuda_runtime.h>
#include <cuda_fp16.h>
#include <math.h>
#include <stdint.h>

#define TT   8192
#define DD   2048
#define FF   1024
#define EE   7
#define CAPX 1170
#define MPAD 1280
#define NST  3
#define STAGE_BYTES 32768           // A 16KB + B 16KB (fp16, 128x64 each)
#define SMEM_BYTES (NST * STAGE_BYTES)
#define SH_TILES 64                 // shared-expert M tiles (8192/128)
#define RT_TILES 10                 // routed M tiles per expert (1280/128)
#define EPI_STRIDE 72               // halfs per staged row (144B: 16B-aligned, bank-shifted)

// ---------------- scratch (device globals) ----------------
__device__ int    g_top[TT * 2];
__device__ float  g_affv[TT * 2];
__device__ int    g_sel_tok[EE * CAPX];
__device__ float  g_sel_w[EE * CAPX];
__device__ __half g_Xr[(size_t)TT * DD];
__device__ __half g_Hs[(size_t)(TT + EE * MPAD) * FF];   // shared rows [0,TT), routed after
__device__ __half g_sw1T[(size_t)2 * FF * DD];
__device__ __half g_sw2T[(size_t)DD * FF];
__device__ __half g_rw1T[(size_t)EE * 2 * FF * DD];
__device__ __half g_rw2T[(size_t)EE * DD * FF];

// ---------------- helpers ----------------
__device__ __forceinline__ uint32_t smem_u32(const void* p) {
    uint32_t a;
    asm("{ .reg .u64 t; cvta.to.shared.u64 t, %1; cvt.u32.u64 %0, t; }" : "=r"(a) : "l"(p));
    return a;
}
__device__ __forceinline__ void cp16(uint32_t d, const void* s) {
    asm volatile("cp.async.cg.shared.global [%0], [%1], 16;" :: "r"(d), "l"(s));
}
#define CP_COMMIT() asm volatile("cp.async.commit_group;" ::: "memory")
#define CP_WAIT1()  asm volatile("cp.async.wait_group 1;" ::: "memory")
#define SWZ(o) ((o) ^ (((o) >> 3) & 0x70))

__device__ __forceinline__ void ldsm4(uint32_t* r, uint32_t addr) {
    asm volatile("ldmatrix.sync.aligned.m8n8.x4.shared.b16 {%0,%1,%2,%3}, [%4];"
                 : "=r"(r[0]), "=r"(r[1]), "=r"(r[2]), "=r"(r[3]) : "r"(addr));
}
__device__ __forceinline__ void mma16816(float* d, const uint32_t* a,
                                         const uint32_t* b) {
    asm volatile(
        "mma.sync.aligned.m16n8k16.row.col.f32.f16.f16.f32 "
        "{%0,%1,%2,%3}, {%4,%5,%6,%7}, {%8,%9}, {%0,%1,%2,%3};"
        : "+f"(d[0]), "+f"(d[1]), "+f"(d[2]), "+f"(d[3])
        : "r"(a[0]), "r"(a[1]), "r"(a[2]), "r"(a[3]), "r"(b[0]), "r"(b[1]));
}

// ---------------- gating (exact fp32) + fused x->fp16 conversion ----------------
__global__ void gating_kernel(const float* __restrict__ x,
                              const float* __restrict__ gw,
                              const float* __restrict__ bias) {
    int t = blockIdx.x;
    const float* xr = x + (size_t)t * DD;
    __half* xh = g_Xr + (size_t)t * DD;
    float s[EE];
#pragma unroll
    for (int e = 0; e < EE; e++) s[e] = 0.f;
    for (int d = threadIdx.x; d < DD; d += 256) {
        float xv = xr[d];
        xh[d] = __float2half_rn(xv);           // fused fp16 copy (coalesced)
#pragma unroll
        for (int e = 0; e < EE; e++) s[e] = fmaf(xv, gw[d * EE + e], s[e]);
    }
#pragma unroll
    for (int off = 16; off > 0; off >>= 1)
#pragma unroll
        for (int e = 0; e < EE; e++)
            s[e] += __shfl_down_sync(0xffffffffu, s[e], off);
    __shared__ float red[8][EE];
    int warp = threadIdx.x >> 5, lane = threadIdx.x & 31;
    if (lane == 0)
#pragma unroll
        for (int e = 0; e < EE; e++) red[warp][e] = s[e];
    __syncthreads();
    if (threadIdx.x == 0) {
        float aff[EE];
#pragma unroll
        for (int e = 0; e < EE; e++) {
            float v = 0.f;
            for (int w = 0; w < 8; w++) v += red[w][e];
            v += bias[e];
            aff[e] = 1.f / (1.f + expf(-v));
        }
        int e0 = 0;
        for (int e = 1; e < EE; e++) if (aff[e] > aff[e0]) e0 = e;
        int e1 = -1;
        for (int e = 0; e < EE; e++) {
            if (e == e0) continue;
            if (e1 < 0 || aff[e] > aff[e1]) e1 = e;
        }
        g_top[2 * t] = e0;  g_top[2 * t + 1] = e1;
        g_affv[2 * t] = aff[e0];  g_affv[2 * t + 1] = aff[e1];
    }
}

// ---------------- per-expert capacity selection: exact radix-select ----------------
__global__ void __launch_bounds__(1024)
select_kernel() {
    const int e = blockIdx.x;
    const int tid = threadIdx.x;
    __shared__ unsigned int bins[256];
    __shared__ unsigned int sPrefix, sRemaining, sCntLess, sCand, sEqN;
    __shared__ unsigned int eqList[1024];

    unsigned int key[8];
    int cand = 0;
#pragma unroll
    for (int i = 0; i < 8; i++) {
        int t = tid + i * 1024;
        unsigned int k = 0xFFFFFFFFu;
        if (g_top[2 * t] == e)          k = ~__float_as_uint(g_affv[2 * t]);
        else if (g_top[2 * t + 1] == e) k = ~__float_as_uint(g_affv[2 * t + 1]);
        key[i] = k;
        if (k != 0xFFFFFFFFu) cand++;
    }
    if (tid == 0) { sCand = 0; sCntLess = 0; sEqN = 0; }
    __syncthreads();
#pragma unroll
    for (int off = 16; off > 0; off >>= 1)
        cand += __shfl_down_sync(0xffffffffu, cand, off);
    if ((tid & 31) == 0) atomicAdd(&sCand, (unsigned int)cand);
    __syncthreads();
    const unsigned int nCand = sCand;
    const unsigned int target = nCand < CAPX ? nCand : CAPX;

    unsigned int T, remaining;
    if (nCand > CAPX) {
        unsigned int prefix = 0, rem = target;
        for (int shift = 24; shift >= 0; shift -= 8) {
            if (tid < 256) bins[tid] = 0;
            __syncthreads();
            unsigned int maskHi = (shift == 24) ? 0u : (0xFFFFFFFFu << (shift + 8));
#pragma unroll
            for (int i = 0; i < 8; i++) {
                unsigned int k = key[i];
                if (k != 0xFFFFFFFFu && (k & maskHi) == prefix)
                    atomicAdd(&bins[(k >> shift) & 0xFFu], 1u);
            }
            __syncthreads();
            if (tid == 0) {
                unsigned int cum = 0, b = 0;
                for (; b < 256; b++) {
                    if (cum + bins[b] >= rem) break;
                    cum += bins[b];
                }
                sPrefix = prefix | (b << shift);
                sRemaining = rem - cum;
            }
            __syncthreads();
            prefix = sPrefix; rem = sRemaining;
            __syncthreads();
        }
        T = prefix; remaining = rem;
    } else {
        T = 0xFFFFFFFFu; remaining = 0;
    }

#pragma unroll
    for (int i = 0; i < 8; i++) {
        unsigned int k = key[i];
        if (k < T) {
            unsigned int slot = atomicAdd(&sCntLess, 1u);
            g_sel_tok[e * CAPX + slot] = tid + i * 1024;
            g_sel_w[e * CAPX + slot]   = __uint_as_float(~k);
        } else if (k == T && k != 0xFFFFFFFFu) {
            unsigned int p = atomicAdd(&sEqN, 1u);
            if (p < 1024) eqList[p] = (unsigned int)(tid + i * 1024);
        }
    }
    __syncthreads();
    if (tid == 0 && remaining > 0) {
        unsigned int m = sEqN; if (m > 1024) m = 1024;
        for (unsigned int a = 1; a < m; a++) {
            unsigned int v = eqList[a]; int b = (int)a - 1;
            while (b >= 0 && eqList[b] > v) { eqList[b + 1] = eqList[b]; b--; }
            eqList[b + 1] = v;
        }
        unsigned int base = target - remaining;
        for (unsigned int j = 0; j < remaining && j < m; j++) {
            g_sel_tok[e * CAPX + base + j] = (int)eqList[j];
            g_sel_w[e * CAPX + base + j]   = __uint_as_float(~T);
        }
    }
    for (unsigned int i = target + tid; i < CAPX; i += 1024) {
        g_sel_tok[e * CAPX + i] = 0;
        g_sel_w[e * CAPX + i]   = 0.f;
    }
}

// ---------------- fused transpose-convert (both weight groups, one launch) ----------------
// z in [0,8): w1 group, K=DD, N=2FF. z in [8,16): w2 group, K=FF, N=DD (y<16 only).
__global__ void __launch_bounds__(256)
convT_all(const float* __restrict__ sw1, const float* __restrict__ rw1,
          const float* __restrict__ sw2, const float* __restrict__ rw2,
          __half* __restrict__ sw1T, __half* __restrict__ rw1T,
          __half* __restrict__ sw2T, __half* __restrict__ rw2T) {
    __shared__ float t[64][65];
    int z = blockIdx.z;
    const float* in; __half* out; int K, N;
    if (z < 8) {
        K = DD; N = 2 * FF;
        in  = (z == 0) ? sw1 : rw1 + (size_t)(z - 1) * K * N;
        out = (z == 0) ? sw1T : rw1T + (size_t)(z - 1) * K * N;
    } else {
        if (blockIdx.y >= FF / 64) return;   // w2 has only 16 y-tiles
        int zz = z - 8;
        K = FF; N = DD;
        in  = (zz == 0) ? sw2 : rw2 + (size_t)(zz - 1) * K * N;
        out = (zz == 0) ? sw2T : rw2T + (size_t)(zz - 1) * K * N;
    }
    int n0 = blockIdx.x * 64, k0 = blockIdx.y * 64;
    int r = threadIdx.x >> 4;
    int c4 = (threadIdx.x & 15) * 4;
#pragma unroll
    for (int p = 0; p < 4; p++) {
        int row = r + p * 16;
        float4 v = *(const float4*)(in + (size_t)(k0 + row) * N + n0 + c4);
        t[row][c4 + 0] = v.x; t[row][c4 + 1] = v.y;
        t[row][c4 + 2] = v.z; t[row][c4 + 3] = v.w;
    }
    __syncthreads();
    int warp = threadIdx.x >> 5, lane = threadIdx.x & 31;
#pragma unroll
    for (int p = 0; p < 8; p++) {
        int n = warp * 8 + p;
        __half2 h = __floats2half2_rn(t[2 * lane][n], t[2 * lane + 1][n]);
        *(__half2*)(out + (size_t)(n0 + n) * K + k0 + 2 * lane) = h;
    }
}

// ================= GEMM1 (templated shared / routed) — SwiGLU + staged epilogue =================
template <bool ROUTED>
__global__ void __launch_bounds__(128, 2)
gemm1_kernel(const __half* __restrict__ A, const __half* __restrict__ B,
             __half* __restrict__ Hs, const int* __restrict__ gidx) {
    extern __shared__ char smem[];
    const uint32_t sb = smem_u32(smem);
    const int tid = threadIdx.x;
    const int lane = tid & 31, wid = tid >> 5;
    const int wm = (wid & 1) * 64;
    const int wn = (wid >> 1) * 64;

    const int by = blockIdx.y;
    const int e   = ROUTED ? by / RT_TILES : 0;
    const int byy = ROUTED ? by - e * RT_TILES : by;

    const __half* Bb = (ROUTED ? B + (size_t)e * 2 * FF * DD : B) +
                       (size_t)blockIdx.x * 64 * DD;
    __half* Hb = Hs + (ROUTED ? (size_t)(TT + e * MPAD) * FF : 0);

    const int kIters = DD >> 6;
    const int lrow = tid >> 3;
    const int lc   = tid & 7;

    int arow_[8];
#pragma unroll
    for (int j = 0; j < 8; j++) {
        int am = byy * 128 + lrow + j * 16;
        if (ROUTED)
            arow_[j] = (am < CAPX) ? gidx[e * CAPX + am] : 0;
        else
            arow_[j] = am;
    }

    auto load_stage = [&](int s, int kt) {
        uint32_t abase = sb + s * STAGE_BYTES;
        uint32_t bbase = abase + 16384;
        const int ko = kt * 64 + lc * 8;
#pragma unroll
        for (int j = 0; j < 8; j++) {
            int r = lrow + j * 16;
            cp16(abase + SWZ(r * 128 + lc * 16), A + (size_t)arow_[j] * DD + ko);
        }
#pragma unroll
        for (int j = 0; j < 8; j++) {
            int r = lrow + j * 16;
            size_t grow = (size_t)(r >> 1) + (size_t)(r & 1) * FF;
            cp16(bbase + SWZ(r * 128 + lc * 16), Bb + grow * DD + ko);
        }
    };

    float acc[4][8][4];
#pragma unroll
    for (int i = 0; i < 4; i++)
#pragma unroll
        for (int j = 0; j < 8; j++)
#pragma unroll
            for (int q = 0; q < 4; q++) acc[i][j][q] = 0.f;

    load_stage(0, 0); CP_COMMIT();
    load_stage(1, 1); CP_COMMIT();

    const int g  = lane >> 3;
    const int l7 = lane & 7;
    const int arow = wm + (g & 1) * 8 + l7;
    const int brow = wn + (g >> 1) * 8 + l7;
    const int acb  = (g >> 1) * 16;
    const int bcb  = (g & 1) * 16;

    for (int kt = 0; kt < kIters; kt++) {
        int s = kt % NST;
        CP_WAIT1();
        __syncthreads();
        if (kt + 2 < kIters) load_stage((kt + 2) % NST, kt + 2);
        CP_COMMIT();

        uint32_t abase = sb + s * STAGE_BYTES;
        uint32_t bbase = abase + 16384;
#pragma unroll
        for (int ks = 0; ks < 4; ks++) {
            uint32_t af[4][4], bf[4][4];
#pragma unroll
            for (int mi = 0; mi < 4; mi++)
                ldsm4(af[mi], abase + SWZ((arow + mi * 16) * 128 + ks * 32 + acb));
#pragma unroll
            for (int p = 0; p < 4; p++)
                ldsm4(bf[p], bbase + SWZ((brow + p * 16) * 128 + ks * 32 + bcb));
#pragma unroll
            for (int mi = 0; mi < 4; mi++)
#pragma unroll
                for (int ni = 0; ni < 8; ni++)
                    mma16816(acc[mi][ni], af[mi], &bf[ni >> 1][(ni & 1) * 2]);
        }
    }

    // ---- staged epilogue: swiglu -> smem tile (conflict-free) -> coalesced Hs ----
    __syncthreads();                       // all warps done with pipeline smem
    __half* sm = (__half*)smem;            // 128 x EPI_STRIDE halfs (18KB of 96KB)
    const int f_loc0 = (wn >> 1) + (lane & 3);
    const int m_loc0 = wm + (lane >> 2);
#pragma unroll
    for (int mi = 0; mi < 4; mi++)
#pragma unroll
        for (int half = 0; half < 2; half++) {
            int mloc = m_loc0 + mi * 16 + half * 8;
#pragma unroll
            for (int ni = 0; ni < 8; ni++) {
                float x1 = acc[mi][ni][half * 2 + 0];
                float x2 = acc[mi][ni][half * 2 + 1];
                float o = x1 * (x2 / (1.f + expf(-x2)));
                sm[mloc * EPI_STRIDE + f_loc0 + ni * 4] = __float2half_rn(o);
            }
        }
    __syncthreads();
    {
        const int m_base = byy * 128;
        const int f_base = blockIdx.x * 64;
        const int rloc = tid >> 3;          // 0..15
        const int chunk = (tid & 7) * 8;    // halfs
#pragma unroll
        for (int it = 0; it < 8; it++) {
            int r = it * 16 + rloc;
            uint4 v = *(const uint4*)&sm[r * EPI_STRIDE + chunk];
            *(uint4*)(Hb + (size_t)(m_base + r) * FF + f_base + chunk) = v;
        }
    }
}

// ================= GEMM2 (templated: dense store OR routed scatter) =================
template <bool ROUTED>
__global__ void __launch_bounds__(128, 2)
gemm2_kernel(const __half* __restrict__ Hs, const __half* __restrict__ B,
             float* __restrict__ out,
             const int* __restrict__ rout, const float* __restrict__ wout) {
    extern __shared__ char smem[];
    const uint32_t sb = smem_u32(smem);
    const int tid = threadIdx.x;
    const int lane = tid & 31, wid = tid >> 5;
    const int wm = (wid & 1) * 64;
    const int wn = (wid >> 1) * 64;

    const int by = blockIdx.y;
    const int e   = ROUTED ? by / RT_TILES : 0;
    const int byy = ROUTED ? by - e * RT_TILES : by;

    const __half* Ab = Hs + (ROUTED ? (size_t)(TT + e * MPAD + byy * 128) * FF
                                    : (size_t)byy * 128 * FF);
    const __half* Bb = (ROUTED ? B + (size_t)e * DD * FF : B) +
                       (size_t)blockIdx.x * 128 * FF;

    const int kIters = FF >> 6;
    const int lrow = tid >> 3;
    const int lc   = tid & 7;

    auto load_stage = [&](int s, int kt) {
        uint32_t abase = sb + s * STAGE_BYTES;
        uint32_t bbase = abase + 16384;
        const int ko = kt * 64 + lc * 8;
#pragma unroll
        for (int j = 0; j < 8; j++) {
            int r = lrow + j * 16;
            cp16(abase + SWZ(r * 128 + lc * 16), Ab + (size_t)r * FF + ko);
        }
#pragma unroll
        for (int j = 0; j < 8; j++) {
            int r = lrow + j * 16;
            cp16(bbase + SWZ(r * 128 + lc * 16), Bb + (size_t)r * FF + ko);
        }
    };

    float acc[4][8][4];
#pragma unroll
    for (int i = 0; i < 4; i++)
#pragma unroll
        for (int j = 0; j < 8; j++)
#pragma unroll
            for (int q = 0; q < 4; q++) acc[i][j][q] = 0.f;

    load_stage(0, 0); CP_COMMIT();
    load_stage(1, 1); CP_COMMIT();

    const int g  = lane >> 3;
    const int l7 = lane & 7;
    const int arow = wm + (g & 1) * 8 + l7;
    const int brow = wn + (g >> 1) * 8 + l7;
    const int acb  = (g >> 1) * 16;
    const int bcb  = (g & 1) * 16;

    for (int kt = 0; kt < kIters; kt++) {
        int s = kt % NST;
        CP_WAIT1();
        __syncthreads();
        if (kt + 2 < kIters) load_stage((kt + 2) % NST, kt + 2);
        CP_COMMIT();

        uint32_t abase = sb + s * STAGE_BYTES;
        uint32_t bbase = abase + 16384;
#pragma unroll
        for (int ks = 0; ks < 4; ks++) {
            uint32_t af[4][4], bf[4][4];
#pragma unroll
            for (int mi = 0; mi < 4; mi++)
                ldsm4(af[mi], abase + SWZ((arow + mi * 16) * 128 + ks * 32 + acb));
#pragma unroll
            for (int p = 0; p < 4; p++)
                ldsm4(bf[p], bbase + SWZ((brow + p * 16) * 128 + ks * 32 + bcb));
#pragma unroll
            for (int mi = 0; mi < 4; mi++)
#pragma unroll
                for (int ni = 0; ni < 8; ni++)
                    mma16816(acc[mi][ni], af[mi], &bf[ni >> 1][(ni & 1) * 2]);
        }
    }

    const int ncol0 = blockIdx.x * 128 + wn + (lane & 3) * 2;
    if (!ROUTED) {
        const int mrow0 = byy * 128 + wm + (lane >> 2);
#pragma unroll
        for (int mi = 0; mi < 4; mi++)
#pragma unroll
            for (int ni = 0; ni < 8; ni++) {
                int rr = mrow0 + mi * 16, cc = ncol0 + ni * 8;
                *(float2*)(out + (size_t)rr * 2048 + cc) =
                    make_float2(acc[mi][ni][0], acc[mi][ni][1]);
                *(float2*)(out + (size_t)(rr + 8) * 2048 + cc) =
                    make_float2(acc[mi][ni][2], acc[mi][ni][3]);
            }
    } else {
#pragma unroll
        for (int mi = 0; mi < 4; mi++)
#pragma unroll
            for (int half = 0; half < 2; half++) {
                int mloc = byy * 128 + wm + mi * 16 + (lane >> 2) + half * 8;
                if (mloc >= CAPX) continue;
                float wgt = wout[e * CAPX + mloc];
                if (wgt == 0.f) continue;
                int tok = rout[e * CAPX + mloc];
                float* orow = out + (size_t)tok * 2048;
#pragma unroll
                for (int ni = 0; ni < 8; ni++) {
                    int cc = ncol0 + ni * 8;
                    atomicAdd(orow + cc,     wgt * acc[mi][ni][half * 2 + 0]);
                    atomicAdd(orow + cc + 1, wgt * acc[mi][ni][half * 2 + 1]);
                }
            }
    }
}

// ---------------- launch ----------------
extern "C" void kernel_launch(void* const* d_in, const int* in_sizes, int n_in,
                              void* d_out, int out_size) {
    const float* x   = (const float*)d_in[0];
    const float* gw  = (const float*)d_in[1];
    const float* eb  = (const float*)d_in[2];
    const float* sw1 = (const float*)d_in[3];
    const float* sw2 = (const float*)d_in[4];
    const float* rw1 = (const float*)d_in[5];
    const float* rw2 = (const float*)d_in[6];
    float* out = (float*)d_out;

    __half *Xr, *Hs, *sw1T, *sw2T, *rw1T, *rw2T;
    float *selw;
    int* seltok;
    cudaGetSymbolAddress((void**)&Xr, g_Xr);
    cudaGetSymbolAddress((void**)&Hs, g_Hs);
    cudaGetSymbolAddress((void**)&sw1T, g_sw1T);
    cudaGetSymbolAddress((void**)&sw2T, g_sw2T);
    cudaGetSymbolAddress((void**)&rw1T, g_rw1T);
    cudaGetSymbolAddress((void**)&rw2T, g_rw2T);
    cudaGetSymbolAddress((void**)&seltok, g_sel_tok);
    cudaGetSymbolAddress((void**)&selw, g_sel_w);

    cudaFuncSetAttribute(gemm1_kernel<false>,
                         cudaFuncAttributeMaxDynamicSharedMemorySize, SMEM_BYTES);
    cudaFuncSetAttribute(gemm1_kernel<true>,
                         cudaFuncAttributeMaxDynamicSharedMemorySize, SMEM_BYTES);
    cudaFuncSetAttribute(gemm2_kernel<false>,
                         cudaFuncAttributeMaxDynamicSharedMemorySize, SMEM_BYTES);
    cudaFuncSetAttribute(gemm2_kernel<true>,
                         cudaFuncAttributeMaxDynamicSharedMemorySize, SMEM_BYTES);

    // 0: gating (+ fused x->fp16)
    gating_kernel<<<TT, 256>>>(x, gw, eb);
    // 1: fused weight transpose-convert (w1 + w2 groups, one launch)
    convT_all<<<dim3(32, 32, 16), 256>>>(
        sw1, rw1, sw2, rw2, sw1T, rw1T, sw2T, rw2T);
    // 2: exact radix-select capacity selection
    select_kernel<<<EE, 1024>>>();
    // 3: shared GEMM1 (SwiGLU, staged coalesced epilogue)  [ncu capture slot]
    gemm1_kernel<false><<<dim3(16, SH_TILES), 128, SMEM_BYTES>>>(
        Xr, sw1T, Hs, nullptr);
    // 4: shared GEMM2 — dense stores (cover every out row fully)
    gemm2_kernel<false><<<dim3(16, SH_TILES), 128, SMEM_BYTES>>>(
        Hs, sw2T, out, nullptr, nullptr);
    // 5: routed GEMM1 (gathered A, SwiGLU, staged epilogue)
    gemm1_kernel<true><<<dim3(16, EE * RT_TILES), 128, SMEM_BYTES>>>(
        Xr, rw1T, Hs, seltok);
    // 6: routed GEMM2 — weighted atomicAdd on top of stored shared result
    gemm2_kernel<true><<<dim3(16, EE * RT_TILES), 128, SMEM_BYTES>>>(
        Hs, rw2T, out, seltok, selw);
}

// round 12
// speedup vs baseline: 1.0409x; 1.0409x over previous
#include <cuda_runtime.h>
#include <cuda_fp16.h>
#include <math.h>
#include <stdint.h>

#define TT   8192
#define DD   2048
#define FF   1024
#define EE   7
#define CAPX 1170
#define MPAD 1280
#define NST  3
#define STAGE_BYTES 32768           // A 16KB + B 16KB (fp16, 128x64 each)
#define SMEM_BYTES (NST * STAGE_BYTES)
#define SH_TILES 64                 // shared-expert M tiles (8192/128)
#define RT_TILES 10                 // routed M tiles per expert (1280/128)

// ---------------- scratch (device globals) ----------------
__device__ int    g_top[TT * 2];
__device__ float  g_affv[TT * 2];
__device__ int    g_sel_tok[EE * CAPX];
__device__ float  g_sel_w[EE * CAPX];
__device__ __half g_Xr[(size_t)TT * DD];
__device__ __half g_Hs[(size_t)(TT + EE * MPAD) * FF];   // shared rows [0,TT), routed after
__device__ __half g_sw1T[(size_t)2 * FF * DD];
__device__ __half g_sw2T[(size_t)DD * FF];
__device__ __half g_rw1T[(size_t)EE * 2 * FF * DD];
__device__ __half g_rw2T[(size_t)EE * DD * FF];

// ---------------- helpers ----------------
__device__ __forceinline__ uint32_t smem_u32(const void* p) {
    uint32_t a;
    asm("{ .reg .u64 t; cvta.to.shared.u64 t, %1; cvt.u32.u64 %0, t; }" : "=r"(a) : "l"(p));
    return a;
}
__device__ __forceinline__ void cp16(uint32_t d, const void* s) {
    asm volatile("cp.async.cg.shared.global [%0], [%1], 16;" :: "r"(d), "l"(s));
}
#define CP_COMMIT() asm volatile("cp.async.commit_group;" ::: "memory")
#define CP_WAIT1()  asm volatile("cp.async.wait_group 1;" ::: "memory")
#define SWZ(o) ((o) ^ (((o) >> 3) & 0x70))

__device__ __forceinline__ void ldsm4(uint32_t* r, uint32_t addr) {
    asm volatile("ldmatrix.sync.aligned.m8n8.x4.shared.b16 {%0,%1,%2,%3}, [%4];"
                 : "=r"(r[0]), "=r"(r[1]), "=r"(r[2]), "=r"(r[3]) : "r"(addr));
}
__device__ __forceinline__ void mma16816(float* d, const uint32_t* a,
                                         const uint32_t* b) {
    asm volatile(
        "mma.sync.aligned.m16n8k16.row.col.f32.f16.f16.f32 "
        "{%0,%1,%2,%3}, {%4,%5,%6,%7}, {%8,%9}, {%0,%1,%2,%3};"
        : "+f"(d[0]), "+f"(d[1]), "+f"(d[2]), "+f"(d[3])
        : "r"(a[0]), "r"(a[1]), "r"(a[2]), "r"(a[3]), "r"(b[0]), "r"(b[1]));
}

// ---------------- gating (exact fp32) + fused x->fp16 conversion ----------------
__global__ void gating_kernel(const float* __restrict__ x,
                              const float* __restrict__ gw,
                              const float* __restrict__ bias) {
    int t = blockIdx.x;
    const float* xr = x + (size_t)t * DD;
    __half* xh = g_Xr + (size_t)t * DD;
    float s[EE];
#pragma unroll
    for (int e = 0; e < EE; e++) s[e] = 0.f;
    for (int d = threadIdx.x; d < DD; d += 256) {
        float xv = xr[d];
        xh[d] = __float2half_rn(xv);           // fused fp16 copy (coalesced)
#pragma unroll
        for (int e = 0; e < EE; e++) s[e] = fmaf(xv, gw[d * EE + e], s[e]);
    }
#pragma unroll
    for (int off = 16; off > 0; off >>= 1)
#pragma unroll
        for (int e = 0; e < EE; e++)
            s[e] += __shfl_down_sync(0xffffffffu, s[e], off);
    __shared__ float red[8][EE];
    int warp = threadIdx.x >> 5, lane = threadIdx.x & 31;
    if (lane == 0)
#pragma unroll
        for (int e = 0; e < EE; e++) red[warp][e] = s[e];
    __syncthreads();
    if (threadIdx.x == 0) {
        float aff[EE];
#pragma unroll
        for (int e = 0; e < EE; e++) {
            float v = 0.f;
            for (int w = 0; w < 8; w++) v += red[w][e];
            v += bias[e];
            aff[e] = 1.f / (1.f + expf(-v));
        }
        int e0 = 0;
        for (int e = 1; e < EE; e++) if (aff[e] > aff[e0]) e0 = e;
        int e1 = -1;
        for (int e = 0; e < EE; e++) {
            if (e == e0) continue;
            if (e1 < 0 || aff[e] > aff[e1]) e1 = e;
        }
        g_top[2 * t] = e0;  g_top[2 * t + 1] = e1;
        g_affv[2 * t] = aff[e0];  g_affv[2 * t + 1] = aff[e1];
    }
}

// ---------------- per-expert capacity selection: exact radix-select ----------------
__global__ void __launch_bounds__(1024)
select_kernel() {
    const int e = blockIdx.x;
    const int tid = threadIdx.x;
    __shared__ unsigned int bins[256];
    __shared__ unsigned int sPrefix, sRemaining, sCntLess, sCand, sEqN;
    __shared__ unsigned int eqList[1024];

    unsigned int key[8];
    int cand = 0;
#pragma unroll
    for (int i = 0; i < 8; i++) {
        int t = tid + i * 1024;
        unsigned int k = 0xFFFFFFFFu;
        if (g_top[2 * t] == e)          k = ~__float_as_uint(g_affv[2 * t]);
        else if (g_top[2 * t + 1] == e) k = ~__float_as_uint(g_affv[2 * t + 1]);
        key[i] = k;
        if (k != 0xFFFFFFFFu) cand++;
    }
    if (tid == 0) { sCand = 0; sCntLess = 0; sEqN = 0; }
    __syncthreads();
#pragma unroll
    for (int off = 16; off > 0; off >>= 1)
        cand += __shfl_down_sync(0xffffffffu, cand, off);
    if ((tid & 31) == 0) atomicAdd(&sCand, (unsigned int)cand);
    __syncthreads();
    const unsigned int nCand = sCand;
    const unsigned int target = nCand < CAPX ? nCand : CAPX;

    unsigned int T, remaining;
    if (nCand > CAPX) {
        unsigned int prefix = 0, rem = target;
        for (int shift = 24; shift >= 0; shift -= 8) {
            if (tid < 256) bins[tid] = 0;
            __syncthreads();
            unsigned int maskHi = (shift == 24) ? 0u : (0xFFFFFFFFu << (shift + 8));
#pragma unroll
            for (int i = 0; i < 8; i++) {
                unsigned int k = key[i];
                if (k != 0xFFFFFFFFu && (k & maskHi) == prefix)
                    atomicAdd(&bins[(k >> shift) & 0xFFu], 1u);
            }
            __syncthreads();
            if (tid == 0) {
                unsigned int cum = 0, b = 0;
                for (; b < 256; b++) {
                    if (cum + bins[b] >= rem) break;
                    cum += bins[b];
                }
                sPrefix = prefix | (b << shift);
                sRemaining = rem - cum;
            }
            __syncthreads();
            prefix = sPrefix; rem = sRemaining;
            __syncthreads();
        }
        T = prefix; remaining = rem;
    } else {
        T = 0xFFFFFFFFu; remaining = 0;
    }

#pragma unroll
    for (int i = 0; i < 8; i++) {
        unsigned int k = key[i];
        if (k < T) {
            unsigned int slot = atomicAdd(&sCntLess, 1u);
            g_sel_tok[e * CAPX + slot] = tid + i * 1024;
            g_sel_w[e * CAPX + slot]   = __uint_as_float(~k);
        } else if (k == T && k != 0xFFFFFFFFu) {
            unsigned int p = atomicAdd(&sEqN, 1u);
            if (p < 1024) eqList[p] = (unsigned int)(tid + i * 1024);
        }
    }
    __syncthreads();
    if (tid == 0 && remaining > 0) {
        unsigned int m = sEqN; if (m > 1024) m = 1024;
        for (unsigned int a = 1; a < m; a++) {
            unsigned int v = eqList[a]; int b = (int)a - 1;
            while (b >= 0 && eqList[b] > v) { eqList[b + 1] = eqList[b]; b--; }
            eqList[b + 1] = v;
        }
        unsigned int base = target - remaining;
        for (unsigned int j = 0; j < remaining && j < m; j++) {
            g_sel_tok[e * CAPX + base + j] = (int)eqList[j];
            g_sel_w[e * CAPX + base + j]   = __uint_as_float(~T);
        }
    }
    for (unsigned int i = target + tid; i < CAPX; i += 1024) {
        g_sel_tok[e * CAPX + i] = 0;
        g_sel_w[e * CAPX + i]   = 0.f;
    }
}

// ---------------- fused transpose-convert (both weight groups, one launch) ----------------
__global__ void __launch_bounds__(256)
convT_all(const float* __restrict__ sw1, const float* __restrict__ rw1,
          const float* __restrict__ sw2, const float* __restrict__ rw2,
          __half* __restrict__ sw1T, __half* __restrict__ rw1T,
          __half* __restrict__ sw2T, __half* __restrict__ rw2T) {
    __shared__ float t[64][65];
    int z = blockIdx.z;
    const float* in; __half* out; int K, N;
    if (z < 8) {
        K = DD; N = 2 * FF;
        in  = (z == 0) ? sw1 : rw1 + (size_t)(z - 1) * K * N;
        out = (z == 0) ? sw1T : rw1T + (size_t)(z - 1) * K * N;
    } else {
        if (blockIdx.y >= FF / 64) return;   // w2 has only 16 y-tiles
        int zz = z - 8;
        K = FF; N = DD;
        in  = (zz == 0) ? sw2 : rw2 + (size_t)(zz - 1) * K * N;
        out = (zz == 0) ? sw2T : rw2T + (size_t)(zz - 1) * K * N;
    }
    int n0 = blockIdx.x * 64, k0 = blockIdx.y * 64;
    if (n0 >= N) return;
    int r = threadIdx.x >> 4;
    int c4 = (threadIdx.x & 15) * 4;
#pragma unroll
    for (int p = 0; p < 4; p++) {
        int row = r + p * 16;
        float4 v = *(const float4*)(in + (size_t)(k0 + row) * N + n0 + c4);
        t[row][c4 + 0] = v.x; t[row][c4 + 1] = v.y;
        t[row][c4 + 2] = v.z; t[row][c4 + 3] = v.w;
    }
    __syncthreads();
    int warp = threadIdx.x >> 5, lane = threadIdx.x & 31;
#pragma unroll
    for (int p = 0; p < 8; p++) {
        int n = warp * 8 + p;
        __half2 h = __floats2half2_rn(t[2 * lane][n], t[2 * lane + 1][n]);
        *(__half2*)(out + (size_t)(n0 + n) * K + k0 + 2 * lane) = h;
    }
}

// ================= GEMM1 (templated shared / routed) — SwiGLU epilogue =================
template <bool ROUTED>
__global__ void __launch_bounds__(128, 2)
gemm1_kernel(const __half* __restrict__ A, const __half* __restrict__ B,
             __half* __restrict__ Hs, const int* __restrict__ gidx) {
    extern __shared__ char smem[];
    const uint32_t sb = smem_u32(smem);
    const int tid = threadIdx.x;
    const int lane = tid & 31, wid = tid >> 5;
    const int wm = (wid & 1) * 64;
    const int wn = (wid >> 1) * 64;

    const int by = blockIdx.y;
    const int e   = ROUTED ? by / RT_TILES : 0;
    const int byy = ROUTED ? by - e * RT_TILES : by;

    const __half* Bb = (ROUTED ? B + (size_t)e * 2 * FF * DD : B) +
                       (size_t)blockIdx.x * 64 * DD;
    __half* Hb = Hs + (ROUTED ? (size_t)(TT + e * MPAD) * FF : 0);

    const int kIters = DD >> 6;
    const int lrow = tid >> 3;
    const int lc   = tid & 7;

    int arow_[8];
#pragma unroll
    for (int j = 0; j < 8; j++) {
        int am = byy * 128 + lrow + j * 16;
        if (ROUTED)
            arow_[j] = (am < CAPX) ? gidx[e * CAPX + am] : 0;
        else
            arow_[j] = am;
    }

    auto load_stage = [&](int s, int kt) {
        uint32_t abase = sb + s * STAGE_BYTES;
        uint32_t bbase = abase + 16384;
        const int ko = kt * 64 + lc * 8;
#pragma unroll
        for (int j = 0; j < 8; j++) {
            int r = lrow + j * 16;
            cp16(abase + SWZ(r * 128 + lc * 16), A + (size_t)arow_[j] * DD + ko);
        }
#pragma unroll
        for (int j = 0; j < 8; j++) {
            int r = lrow + j * 16;
            size_t grow = (size_t)(r >> 1) + (size_t)(r & 1) * FF;
            cp16(bbase + SWZ(r * 128 + lc * 16), Bb + grow * DD + ko);
        }
    };

    float acc[4][8][4];
#pragma unroll
    for (int i = 0; i < 4; i++)
#pragma unroll
        for (int j = 0; j < 8; j++)
#pragma unroll
            for (int q = 0; q < 4; q++) acc[i][j][q] = 0.f;

    load_stage(0, 0); CP_COMMIT();
    load_stage(1, 1); CP_COMMIT();

    const int g  = lane >> 3;
    const int l7 = lane & 7;
    const int arow = wm + (g & 1) * 8 + l7;
    const int brow = wn + (g >> 1) * 8 + l7;
    const int acb  = (g >> 1) * 16;
    const int bcb  = (g & 1) * 16;

    for (int kt = 0; kt < kIters; kt++) {
        int s = kt % NST;
        CP_WAIT1();
        __syncthreads();
        if (kt + 2 < kIters) load_stage((kt + 2) % NST, kt + 2);
        CP_COMMIT();

        uint32_t abase = sb + s * STAGE_BYTES;
        uint32_t bbase = abase + 16384;
#pragma unroll
        for (int ks = 0; ks < 4; ks++) {
            uint32_t af[4][4], bf[4][4];
#pragma unroll
            for (int mi = 0; mi < 4; mi++)
                ldsm4(af[mi], abase + SWZ((arow + mi * 16) * 128 + ks * 32 + acb));
#pragma unroll
            for (int p = 0; p < 4; p++)
                ldsm4(bf[p], bbase + SWZ((brow + p * 16) * 128 + ks * 32 + bcb));
#pragma unroll
            for (int mi = 0; mi < 4; mi++)
#pragma unroll
                for (int ni = 0; ni < 8; ni++)
                    mma16816(acc[mi][ni], af[mi], &bf[ni >> 1][(ni & 1) * 2]);
        }
    }

    // epilogue (R10 direct-store form): acc pair (2j,2j+1) = (x1,x2) -> swiglu -> fp16
    const int f0 = blockIdx.x * 64 + (wn >> 1) + (lane & 3);
    const int m0 = byy * 128 + wm + (lane >> 2);
#pragma unroll
    for (int mi = 0; mi < 4; mi++)
#pragma unroll
        for (int half = 0; half < 2; half++) {
            int m = m0 + mi * 16 + half * 8;
            __half* hrow = Hb + (size_t)m * FF;
#pragma unroll
            for (int ni = 0; ni < 8; ni++) {
                float x1 = acc[mi][ni][half * 2 + 0];
                float x2 = acc[mi][ni][half * 2 + 1];
                float o = x1 * (x2 / (1.f + expf(-x2)));
                hrow[f0 + ni * 4] = __float2half_rn(o);
            }
        }
}

// ================= GEMM2 (templated: dense store OR routed scatter) =================
template <bool ROUTED>
__global__ void __launch_bounds__(128, 2)
gemm2_kernel(const __half* __restrict__ Hs, const __half* __restrict__ B,
             float* __restrict__ out,
             const int* __restrict__ rout, const float* __restrict__ wout) {
    extern __shared__ char smem[];
    const uint32_t sb = smem_u32(smem);
    const int tid = threadIdx.x;
    const int lane = tid & 31, wid = tid >> 5;
    const int wm = (wid & 1) * 64;
    const int wn = (wid >> 1) * 64;

    const int by = blockIdx.y;
    const int e   = ROUTED ? by / RT_TILES : 0;
    const int byy = ROUTED ? by - e * RT_TILES : by;

    const __half* Ab = Hs + (ROUTED ? (size_t)(TT + e * MPAD + byy * 128) * FF
                                    : (size_t)byy * 128 * FF);
    const __half* Bb = (ROUTED ? B + (size_t)e * DD * FF : B) +
                       (size_t)blockIdx.x * 128 * FF;

    const int kIters = FF >> 6;
    const int lrow = tid >> 3;
    const int lc   = tid & 7;

    auto load_stage = [&](int s, int kt) {
        uint32_t abase = sb + s * STAGE_BYTES;
        uint32_t bbase = abase + 16384;
        const int ko = kt * 64 + lc * 8;
#pragma unroll
        for (int j = 0; j < 8; j++) {
            int r = lrow + j * 16;
            cp16(abase + SWZ(r * 128 + lc * 16), Ab + (size_t)r * FF + ko);
        }
#pragma unroll
        for (int j = 0; j < 8; j++) {
            int r = lrow + j * 16;
            cp16(bbase + SWZ(r * 128 + lc * 16), Bb + (size_t)r * FF + ko);
        }
    };

    float acc[4][8][4];
#pragma unroll
    for (int i = 0; i < 4; i++)
#pragma unroll
        for (int j = 0; j < 8; j++)
#pragma unroll
            for (int q = 0; q < 4; q++) acc[i][j][q] = 0.f;

    load_stage(0, 0); CP_COMMIT();
    load_stage(1, 1); CP_COMMIT();

    const int g  = lane >> 3;
    const int l7 = lane & 7;
    const int arow = wm + (g & 1) * 8 + l7;
    const int brow = wn + (g >> 1) * 8 + l7;
    const int acb  = (g >> 1) * 16;
    const int bcb  = (g & 1) * 16;

    for (int kt = 0; kt < kIters; kt++) {
        int s = kt % NST;
        CP_WAIT1();
        __syncthreads();
        if (kt + 2 < kIters) load_stage((kt + 2) % NST, kt + 2);
        CP_COMMIT();

        uint32_t abase = sb + s * STAGE_BYTES;
        uint32_t bbase = abase + 16384;
#pragma unroll
        for (int ks = 0; ks < 4; ks++) {
            uint32_t af[4][4], bf[4][4];
#pragma unroll
            for (int mi = 0; mi < 4; mi++)
                ldsm4(af[mi], abase + SWZ((arow + mi * 16) * 128 + ks * 32 + acb));
#pragma unroll
            for (int p = 0; p < 4; p++)
                ldsm4(bf[p], bbase + SWZ((brow + p * 16) * 128 + ks * 32 + bcb));
#pragma unroll
            for (int mi = 0; mi < 4; mi++)
#pragma unroll
                for (int ni = 0; ni < 8; ni++)
                    mma16816(acc[mi][ni], af[mi], &bf[ni >> 1][(ni & 1) * 2]);
        }
    }

    const int ncol0 = blockIdx.x * 128 + wn + (lane & 3) * 2;
    if (!ROUTED) {
        const int mrow0 = byy * 128 + wm + (lane >> 2);
#pragma unroll
        for (int mi = 0; mi < 4; mi++)
#pragma unroll
            for (int ni = 0; ni < 8; ni++) {
                int rr = mrow0 + mi * 16, cc = ncol0 + ni * 8;
                *(float2*)(out + (size_t)rr * 2048 + cc) =
                    make_float2(acc[mi][ni][0], acc[mi][ni][1]);
                *(float2*)(out + (size_t)(rr + 8) * 2048 + cc) =
                    make_float2(acc[mi][ni][2], acc[mi][ni][3]);
            }
    } else {
#pragma unroll
        for (int mi = 0; mi < 4; mi++)
#pragma unroll
            for (int half = 0; half < 2; half++) {
                int mloc = byy * 128 + wm + mi * 16 + (lane >> 2) + half * 8;
                if (mloc >= CAPX) continue;
                float wgt = wout[e * CAPX + mloc];
                if (wgt == 0.f) continue;
                int tok = rout[e * CAPX + mloc];
                float* orow = out + (size_t)tok * 2048;
#pragma unroll
                for (int ni = 0; ni < 8; ni++) {
                    int cc = ncol0 + ni * 8;
                    atomicAdd(orow + cc,     wgt * acc[mi][ni][half * 2 + 0]);
                    atomicAdd(orow + cc + 1, wgt * acc[mi][ni][half * 2 + 1]);
                }
            }
    }
}

// ---------------- launch (two-stream fork/join, graph-capturable) ----------------
extern "C" void kernel_launch(void* const* d_in, const int* in_sizes, int n_in,
                              void* d_out, int out_size) {
    const float* x   = (const float*)d_in[0];
    const float* gw  = (const float*)d_in[1];
    const float* eb  = (const float*)d_in[2];
    const float* sw1 = (const float*)d_in[3];
    const float* sw2 = (const float*)d_in[4];
    const float* rw1 = (const float*)d_in[5];
    const float* rw2 = (const float*)d_in[6];
    float* out = (float*)d_out;

    __half *Xr, *Hs, *sw1T, *sw2T, *rw1T, *rw2T;
    float *selw;
    int* seltok;
    cudaGetSymbolAddress((void**)&Xr, g_Xr);
    cudaGetSymbolAddress((void**)&Hs, g_Hs);
    cudaGetSymbolAddress((void**)&sw1T, g_sw1T);
    cudaGetSymbolAddress((void**)&sw2T, g_sw2T);
    cudaGetSymbolAddress((void**)&rw1T, g_rw1T);
    cudaGetSymbolAddress((void**)&rw2T, g_rw2T);
    cudaGetSymbolAddress((void**)&seltok, g_sel_tok);
    cudaGetSymbolAddress((void**)&selw, g_sel_w);

    cudaFuncSetAttribute(gemm1_kernel<false>,
                         cudaFuncAttributeMaxDynamicSharedMemorySize, SMEM_BYTES);
    cudaFuncSetAttribute(gemm1_kernel<true>,
                         cudaFuncAttributeMaxDynamicSharedMemorySize, SMEM_BYTES);
    cudaFuncSetAttribute(gemm2_kernel<false>,
                         cudaFuncAttributeMaxDynamicSharedMemorySize, SMEM_BYTES);
    cudaFuncSetAttribute(gemm2_kernel<true>,
                         cudaFuncAttributeMaxDynamicSharedMemorySize, SMEM_BYTES);

    // kernel_launch runs only ~2-3x (correctness + capture); replays execute the
    // graph. Streams/events are created per call and intentionally not destroyed
    // (destroying a capture-joined stream mid-capture is illegal).
    cudaStream_t s2;
    cudaStreamCreateWithFlags(&s2, cudaStreamNonBlocking);
    cudaEvent_t eFork, eW, eSel, eS2, eR2;
    cudaEventCreateWithFlags(&eFork, cudaEventDisableTiming);
    cudaEventCreateWithFlags(&eW,    cudaEventDisableTiming);
    cudaEventCreateWithFlags(&eSel,  cudaEventDisableTiming);
    cudaEventCreateWithFlags(&eS2,   cudaEventDisableTiming);
    cudaEventCreateWithFlags(&eR2,   cudaEventDisableTiming);

    // fork s2 from the (capturing) default stream
    cudaEventRecord(eFork, 0);
    cudaStreamWaitEvent(s2, eFork, 0);

    // s2: weight transpose-convert (independent of gating)
    convT_all<<<dim3(32, 32, 16), 256, 0, s2>>>(
        sw1, rw1, sw2, rw2, sw1T, rw1T, sw2T, rw2T);
    cudaEventRecord(eW, s2);

    // s0: gating (+x->fp16), selection
    gating_kernel<<<TT, 256, 0, 0>>>(x, gw, eb);
    select_kernel<<<EE, 1024, 0, 0>>>();
    cudaEventRecord(eSel, 0);

    // s0: shared chain (needs weights)
    cudaStreamWaitEvent(0, eW, 0);
    gemm1_kernel<false><<<dim3(16, SH_TILES), 128, SMEM_BYTES, 0>>>(
        Xr, sw1T, Hs, nullptr);
    gemm2_kernel<false><<<dim3(16, SH_TILES), 128, SMEM_BYTES, 0>>>(
        Hs, sw2T, out, nullptr, nullptr);
    cudaEventRecord(eS2, 0);

    // s2: routed chain (needs gating+select; weights already in-order on s2)
    cudaStreamWaitEvent(s2, eSel, 0);
    gemm1_kernel<true><<<dim3(16, EE * RT_TILES), 128, SMEM_BYTES, s2>>>(
        Xr, rw1T, Hs, seltok);
    cudaStreamWaitEvent(s2, eS2, 0);      // routed scatter strictly after dense stores
    gemm2_kernel<true><<<dim3(16, EE * RT_TILES), 128, SMEM_BYTES, s2>>>(
        Hs, rw2T, out, seltok, selw);
    cudaEventRecord(eR2, s2);

    // join back to the origin stream
    cudaStreamWaitEvent(0, eR2, 0);
}

// round 14
// speedup vs baseline: 1.1470x; 1.1019x over previous
#include <cuda_runtime.h>
#include <cuda_fp16.h>
#include <math.h>
#include <stdint.h>

#define TT   8192
#define DD   2048
#define FF   1024
#define EE   7
#define CAPX 1170
#define MPAD 1280
#define NST  3
#define STAGE_BYTES 32768           // A 16KB + B 16KB (fp16, 128x64 each)
#define SMEM_BYTES (NST * STAGE_BYTES)
#define SH_TILES 64                 // shared-expert M tiles (8192/128)
#define RT_TILES 10                 // routed M tiles per expert (1280/128)

// ---------------- scratch (device globals) ----------------
__device__ int    g_top[TT * 2];
__device__ float  g_affv[TT * 2];
__device__ int    g_sel_tok[EE * CAPX];
__device__ float  g_sel_w[EE * CAPX];
__device__ __half g_Xr[(size_t)TT * DD];
__device__ __half g_Hs[(size_t)(TT + EE * MPAD) * FF];   // shared rows [0,TT), routed after
__device__ __half g_sw1T[(size_t)2 * FF * DD];
__device__ __half g_sw2T[(size_t)DD * FF];
__device__ __half g_rw1T[(size_t)EE * 2 * FF * DD];
__device__ __half g_rw2T[(size_t)EE * DD * FF];

// ---------------- helpers ----------------
__device__ __forceinline__ uint32_t smem_u32(const void* p) {
    uint32_t a;
    asm("{ .reg .u64 t; cvta.to.shared.u64 t, %1; cvt.u32.u64 %0, t; }" : "=r"(a) : "l"(p));
    return a;
}
__device__ __forceinline__ void cp16(uint32_t d, const void* s) {
    asm volatile("cp.async.cg.shared.global [%0], [%1], 16;" :: "r"(d), "l"(s));
}
#define CP_COMMIT() asm volatile("cp.async.commit_group;" ::: "memory")
#define CP_WAIT1()  asm volatile("cp.async.wait_group 1;" ::: "memory")
#define SWZ(o) ((o) ^ (((o) >> 3) & 0x70))

__device__ __forceinline__ void ldsm4(uint32_t* r, uint32_t addr) {
    asm volatile("ldmatrix.sync.aligned.m8n8.x4.shared.b16 {%0,%1,%2,%3}, [%4];"
                 : "=r"(r[0]), "=r"(r[1]), "=r"(r[2]), "=r"(r[3]) : "r"(addr));
}
__device__ __forceinline__ void mma16816(float* d, const uint32_t* a,
                                         const uint32_t* b) {
    asm volatile(
        "mma.sync.aligned.m16n8k16.row.col.f32.f16.f16.f32 "
        "{%0,%1,%2,%3}, {%4,%5,%6,%7}, {%8,%9}, {%0,%1,%2,%3};"
        : "+f"(d[0]), "+f"(d[1]), "+f"(d[2]), "+f"(d[3])
        : "r"(a[0]), "r"(a[1]), "r"(a[2]), "r"(a[3]), "r"(b[0]), "r"(b[1]));
}

// ---------------- gating (exact fp32) + fused x->fp16 conversion ----------------
__global__ void gating_kernel(const float* __restrict__ x,
                              const float* __restrict__ gw,
                              const float* __restrict__ bias) {
    int t = blockIdx.x;
    const float* xr = x + (size_t)t * DD;
    __half* xh = g_Xr + (size_t)t * DD;
    float s[EE];
#pragma unroll
    for (int e = 0; e < EE; e++) s[e] = 0.f;
    for (int d = threadIdx.x; d < DD; d += 256) {
        float xv = xr[d];
        xh[d] = __float2half_rn(xv);           // fused fp16 copy (coalesced)
#pragma unroll
        for (int e = 0; e < EE; e++) s[e] = fmaf(xv, gw[d * EE + e], s[e]);
    }
#pragma unroll
    for (int off = 16; off > 0; off >>= 1)
#pragma unroll
        for (int e = 0; e < EE; e++)
            s[e] += __shfl_down_sync(0xffffffffu, s[e], off);
    __shared__ float red[8][EE];
    int warp = threadIdx.x >> 5, lane = threadIdx.x & 31;
    if (lane == 0)
#pragma unroll
        for (int e = 0; e < EE; e++) red[warp][e] = s[e];
    __syncthreads();
    if (threadIdx.x == 0) {
        float aff[EE];
#pragma unroll
        for (int e = 0; e < EE; e++) {
            float v = 0.f;
            for (int w = 0; w < 8; w++) v += red[w][e];
            v += bias[e];
            aff[e] = 1.f / (1.f + expf(-v));
        }
        int e0 = 0;
        for (int e = 1; e < EE; e++) if (aff[e] > aff[e0]) e0 = e;
        int e1 = -1;
        for (int e = 0; e < EE; e++) {
            if (e == e0) continue;
            if (e1 < 0 || aff[e] > aff[e1]) e1 = e;
        }
        g_top[2 * t] = e0;  g_top[2 * t + 1] = e1;
        g_affv[2 * t] = aff[e0];  g_affv[2 * t + 1] = aff[e1];
    }
}

// ---------------- per-expert capacity selection: exact radix-select ----------------
__global__ void __launch_bounds__(1024)
select_kernel() {
    const int e = blockIdx.x;
    const int tid = threadIdx.x;
    __shared__ unsigned int bins[256];
    __shared__ unsigned int sPrefix, sRemaining, sCntLess, sCand, sEqN;
    __shared__ unsigned int eqList[1024];

    unsigned int key[8];
    int cand = 0;
#pragma unroll
    for (int i = 0; i < 8; i++) {
        int t = tid + i * 1024;
        unsigned int k = 0xFFFFFFFFu;
        if (g_top[2 * t] == e)          k = ~__float_as_uint(g_affv[2 * t]);
        else if (g_top[2 * t + 1] == e) k = ~__float_as_uint(g_affv[2 * t + 1]);
        key[i] = k;
        if (k != 0xFFFFFFFFu) cand++;
    }
    if (tid == 0) { sCand = 0; sCntLess = 0; sEqN = 0; }
    __syncthreads();
#pragma unroll
    for (int off = 16; off > 0; off >>= 1)
        cand += __shfl_down_sync(0xffffffffu, cand, off);
    if ((tid & 31) == 0) atomicAdd(&sCand, (unsigned int)cand);
    __syncthreads();
    const unsigned int nCand = sCand;
    const unsigned int target = nCand < CAPX ? nCand : CAPX;

    unsigned int T, remaining;
    if (nCand > CAPX) {
        unsigned int prefix = 0, rem = target;
        for (int shift = 24; shift >= 0; shift -= 8) {
            if (tid < 256) bins[tid] = 0;
            __syncthreads();
            unsigned int maskHi = (shift == 24) ? 0u : (0xFFFFFFFFu << (shift + 8));
#pragma unroll
            for (int i = 0; i < 8; i++) {
                unsigned int k = key[i];
                if (k != 0xFFFFFFFFu && (k & maskHi) == prefix)
                    atomicAdd(&bins[(k >> shift) & 0xFFu], 1u);
            }
            __syncthreads();
            if (tid == 0) {
                unsigned int cum = 0, b = 0;
                for (; b < 256; b++) {
                    if (cum + bins[b] >= rem) break;
                    cum += bins[b];
                }
                sPrefix = prefix | (b << shift);
                sRemaining = rem - cum;
            }
            __syncthreads();
            prefix = sPrefix; rem = sRemaining;
            __syncthreads();
        }
        T = prefix; remaining = rem;
    } else {
        T = 0xFFFFFFFFu; remaining = 0;
    }

#pragma unroll
    for (int i = 0; i < 8; i++) {
        unsigned int k = key[i];
        if (k < T) {
            unsigned int slot = atomicAdd(&sCntLess, 1u);
            g_sel_tok[e * CAPX + slot] = tid + i * 1024;
            g_sel_w[e * CAPX + slot]   = __uint_as_float(~k);
        } else if (k == T && k != 0xFFFFFFFFu) {
            unsigned int p = atomicAdd(&sEqN, 1u);
            if (p < 1024) eqList[p] = (unsigned int)(tid + i * 1024);
        }
    }
    __syncthreads();
    if (tid == 0 && remaining > 0) {
        unsigned int m = sEqN; if (m > 1024) m = 1024;
        for (unsigned int a = 1; a < m; a++) {
            unsigned int v = eqList[a]; int b = (int)a - 1;
            while (b >= 0 && eqList[b] > v) { eqList[b + 1] = eqList[b]; b--; }
            eqList[b + 1] = v;
        }
        unsigned int base = target - remaining;
        for (unsigned int j = 0; j < remaining && j < m; j++) {
            g_sel_tok[e * CAPX + base + j] = (int)eqList[j];
            g_sel_w[e * CAPX + base + j]   = __uint_as_float(~T);
        }
    }
    for (unsigned int i = target + tid; i < CAPX; i += 1024) {
        g_sel_tok[e * CAPX + i] = 0;
        g_sel_w[e * CAPX + i]   = 0.f;
    }
}

// ---------------- transpose-convert: single matrix [K,N] fp32 -> [N,K] fp16 ----------------
__global__ void __launch_bounds__(256)
convT_one(const float* __restrict__ in, __half* __restrict__ out, int K, int N) {
    __shared__ float t[64][65];
    int n0 = blockIdx.x * 64, k0 = blockIdx.y * 64;
    int r = threadIdx.x >> 4;
    int c4 = (threadIdx.x & 15) * 4;
#pragma unroll
    for (int p = 0; p < 4; p++) {
        int row = r + p * 16;
        float4 v = *(const float4*)(in + (size_t)(k0 + row) * N + n0 + c4);
        t[row][c4 + 0] = v.x; t[row][c4 + 1] = v.y;
        t[row][c4 + 2] = v.z; t[row][c4 + 3] = v.w;
    }
    __syncthreads();
    int warp = threadIdx.x >> 5, lane = threadIdx.x & 31;
#pragma unroll
    for (int p = 0; p < 8; p++) {
        int n = warp * 8 + p;
        __half2 h = __floats2half2_rn(t[2 * lane][n], t[2 * lane + 1][n]);
        *(__half2*)(out + (size_t)(n0 + n) * K + k0 + 2 * lane) = h;
    }
}

// ---------------- transpose-convert: remaining weights (rw1, sw2, rw2) ----------------
// z<7: rw1 expert z (K=DD,N=2FF). z>=7: zz=z-7 -> w2 group (K=FF,N=DD; y<16).
__global__ void __launch_bounds__(256)
convT_rest(const float* __restrict__ rw1, const float* __restrict__ sw2,
           const float* __restrict__ rw2,
           __half* __restrict__ rw1T, __half* __restrict__ sw2T,
           __half* __restrict__ rw2T) {
    __shared__ float t[64][65];
    int z = blockIdx.z;
    const float* in; __half* out; int K, N;
    if (z < 7) {
        K = DD; N = 2 * FF;
        in  = rw1 + (size_t)z * K * N;
        out = rw1T + (size_t)z * K * N;
    } else {
        if (blockIdx.y >= FF / 64) return;
        int zz = z - 7;
        K = FF; N = DD;
        in  = (zz == 0) ? sw2 : rw2 + (size_t)(zz - 1) * K * N;
        out = (zz == 0) ? sw2T : rw2T + (size_t)(zz - 1) * K * N;
    }
    int n0 = blockIdx.x * 64, k0 = blockIdx.y * 64;
    int r = threadIdx.x >> 4;
    int c4 = (threadIdx.x & 15) * 4;
#pragma unroll
    for (int p = 0; p < 4; p++) {
        int row = r + p * 16;
        float4 v = *(const float4*)(in + (size_t)(k0 + row) * N + n0 + c4);
        t[row][c4 + 0] = v.x; t[row][c4 + 1] = v.y;
        t[row][c4 + 2] = v.z; t[row][c4 + 3] = v.w;
    }
    __syncthreads();
    int warp = threadIdx.x >> 5, lane = threadIdx.x & 31;
#pragma unroll
    for (int p = 0; p < 8; p++) {
        int n = warp * 8 + p;
        __half2 h = __floats2half2_rn(t[2 * lane][n], t[2 * lane + 1][n]);
        *(__half2*)(out + (size_t)(n0 + n) * K + k0 + 2 * lane) = h;
    }
}

// ================= GEMM1 (templated shared / routed) — SwiGLU epilogue =================
template <bool ROUTED>
__global__ void __launch_bounds__(128, 2)
gemm1_kernel(const __half* __restrict__ A, const __half* __restrict__ B,
             __half* __restrict__ Hs, const int* __restrict__ gidx) {
    extern __shared__ char smem[];
    const uint32_t sb = smem_u32(smem);
    const int tid = threadIdx.x;
    const int lane = tid & 31, wid = tid >> 5;
    const int wm = (wid & 1) * 64;
    const int wn = (wid >> 1) * 64;

    const int by = blockIdx.y;
    const int e   = ROUTED ? by / RT_TILES : 0;
    const int byy = ROUTED ? by - e * RT_TILES : by;

    const __half* Bb = (ROUTED ? B + (size_t)e * 2 * FF * DD : B) +
                       (size_t)blockIdx.x * 64 * DD;
    __half* Hb = Hs + (ROUTED ? (size_t)(TT + e * MPAD) * FF : 0);

    const int kIters = DD >> 6;
    const int lrow = tid >> 3;
    const int lc   = tid & 7;

    int arow_[8];
#pragma unroll
    for (int j = 0; j < 8; j++) {
        int am = byy * 128 + lrow + j * 16;
        if (ROUTED)
            arow_[j] = (am < CAPX) ? gidx[e * CAPX + am] : 0;
        else
            arow_[j] = am;
    }

    auto load_stage = [&](int s, int kt) {
        uint32_t abase = sb + s * STAGE_BYTES;
        uint32_t bbase = abase + 16384;
        const int ko = kt * 64 + lc * 8;
#pragma unroll
        for (int j = 0; j < 8; j++) {
            int r = lrow + j * 16;
            cp16(abase + SWZ(r * 128 + lc * 16), A + (size_t)arow_[j] * DD + ko);
        }
#pragma unroll
        for (int j = 0; j < 8; j++) {
            int r = lrow + j * 16;
            size_t grow = (size_t)(r >> 1) + (size_t)(r & 1) * FF;
            cp16(bbase + SWZ(r * 128 + lc * 16), Bb + grow * DD + ko);
        }
    };

    float acc[4][8][4];
#pragma unroll
    for (int i = 0; i < 4; i++)
#pragma unroll
        for (int j = 0; j < 8; j++)
#pragma unroll
            for (int q = 0; q < 4; q++) acc[i][j][q] = 0.f;

    load_stage(0, 0); CP_COMMIT();
    load_stage(1, 1); CP_COMMIT();

    const int g  = lane >> 3;
    const int l7 = lane & 7;
    const int arow = wm + (g & 1) * 8 + l7;
    const int brow = wn + (g >> 1) * 8 + l7;
    const int acb  = (g >> 1) * 16;
    const int bcb  = (g & 1) * 16;

    for (int kt = 0; kt < kIters; kt++) {
        int s = kt % NST;
        CP_WAIT1();
        __syncthreads();
        if (kt + 2 < kIters) load_stage((kt + 2) % NST, kt + 2);
        CP_COMMIT();

        uint32_t abase = sb + s * STAGE_BYTES;
        uint32_t bbase = abase + 16384;
#pragma unroll
        for (int ks = 0; ks < 4; ks++) {
            uint32_t af[4][4], bf[4][4];
#pragma unroll
            for (int mi = 0; mi < 4; mi++)
                ldsm4(af[mi], abase + SWZ((arow + mi * 16) * 128 + ks * 32 + acb));
#pragma unroll
            for (int p = 0; p < 4; p++)
                ldsm4(bf[p], bbase + SWZ((brow + p * 16) * 128 + ks * 32 + bcb));
#pragma unroll
            for (int mi = 0; mi < 4; mi++)
#pragma unroll
                for (int ni = 0; ni < 8; ni++)
                    mma16816(acc[mi][ni], af[mi], &bf[ni >> 1][(ni & 1) * 2]);
        }
    }

    // epilogue: acc pair (2j,2j+1) = (x1,x2) -> swiglu -> fp16 direct stores
    const int f0 = blockIdx.x * 64 + (wn >> 1) + (lane & 3);
    const int m0 = byy * 128 + wm + (lane >> 2);
#pragma unroll
    for (int mi = 0; mi < 4; mi++)
#pragma unroll
        for (int half = 0; half < 2; half++) {
            int m = m0 + mi * 16 + half * 8;
            __half* hrow = Hb + (size_t)m * FF;
#pragma unroll
            for (int ni = 0; ni < 8; ni++) {
                float x1 = acc[mi][ni][half * 2 + 0];
                float x2 = acc[mi][ni][half * 2 + 1];
                float o = x1 * (x2 / (1.f + expf(-x2)));
                hrow[f0 + ni * 4] = __float2half_rn(o);
            }
        }
}

// ================= GEMM2 (templated: dense store OR routed scatter) =================
template <bool ROUTED>
__global__ void __launch_bounds__(128, 2)
gemm2_kernel(const __half* __restrict__ Hs, const __half* __restrict__ B,
             float* __restrict__ out,
             const int* __restrict__ rout, const float* __restrict__ wout) {
    extern __shared__ char smem[];
    const uint32_t sb = smem_u32(smem);
    const int tid = threadIdx.x;
    const int lane = tid & 31, wid = tid >> 5;
    const int wm = (wid & 1) * 64;
    const int wn = (wid >> 1) * 64;

    const int by = blockIdx.y;
    const int e   = ROUTED ? by / RT_TILES : 0;
    const int byy = ROUTED ? by - e * RT_TILES : by;

    const __half* Ab = Hs + (ROUTED ? (size_t)(TT + e * MPAD + byy * 128) * FF
                                    : (size_t)byy * 128 * FF);
    const __half* Bb = (ROUTED ? B + (size_t)e * DD * FF : B) +
                       (size_t)blockIdx.x * 128 * FF;

    const int kIters = FF >> 6;
    const int lrow = tid >> 3;
    const int lc   = tid & 7;

    auto load_stage = [&](int s, int kt) {
        uint32_t abase = sb + s * STAGE_BYTES;
        uint32_t bbase = abase + 16384;
        const int ko = kt * 64 + lc * 8;
#pragma unroll
        for (int j = 0; j < 8; j++) {
            int r = lrow + j * 16;
            cp16(abase + SWZ(r * 128 + lc * 16), Ab + (size_t)r * FF + ko);
        }
#pragma unroll
        for (int j = 0; j < 8; j++) {
            int r = lrow + j * 16;
            cp16(bbase + SWZ(r * 128 + lc * 16), Bb + (size_t)r * FF + ko);
        }
    };

    float acc[4][8][4];
#pragma unroll
    for (int i = 0; i < 4; i++)
#pragma unroll
        for (int j = 0; j < 8; j++)
#pragma unroll
            for (int q = 0; q < 4; q++) acc[i][j][q] = 0.f;

    load_stage(0, 0); CP_COMMIT();
    load_stage(1, 1); CP_COMMIT();

    const int g  = lane >> 3;
    const int l7 = lane & 7;
    const int arow = wm + (g & 1) * 8 + l7;
    const int brow = wn + (g >> 1) * 8 + l7;
    const int acb  = (g >> 1) * 16;
    const int bcb  = (g & 1) * 16;

    for (int kt = 0; kt < kIters; kt++) {
        int s = kt % NST;
        CP_WAIT1();
        __syncthreads();
        if (kt + 2 < kIters) load_stage((kt + 2) % NST, kt + 2);
        CP_COMMIT();

        uint32_t abase = sb + s * STAGE_BYTES;
        uint32_t bbase = abase + 16384;
#pragma unroll
        for (int ks = 0; ks < 4; ks++) {
            uint32_t af[4][4], bf[4][4];
#pragma unroll
            for (int mi = 0; mi < 4; mi++)
                ldsm4(af[mi], abase + SWZ((arow + mi * 16) * 128 + ks * 32 + acb));
#pragma unroll
            for (int p = 0; p < 4; p++)
                ldsm4(bf[p], bbase + SWZ((brow + p * 16) * 128 + ks * 32 + bcb));
#pragma unroll
            for (int mi = 0; mi < 4; mi++)
#pragma unroll
                for (int ni = 0; ni < 8; ni++)
                    mma16816(acc[mi][ni], af[mi], &bf[ni >> 1][(ni & 1) * 2]);
        }
    }

    const int ncol0 = blockIdx.x * 128 + wn + (lane & 3) * 2;
    if (!ROUTED) {
        const int mrow0 = byy * 128 + wm + (lane >> 2);
#pragma unroll
        for (int mi = 0; mi < 4; mi++)
#pragma unroll
            for (int ni = 0; ni < 8; ni++) {
                int rr = mrow0 + mi * 16, cc = ncol0 + ni * 8;
                *(float2*)(out + (size_t)rr * 2048 + cc) =
                    make_float2(acc[mi][ni][0], acc[mi][ni][1]);
                *(float2*)(out + (size_t)(rr + 8) * 2048 + cc) =
                    make_float2(acc[mi][ni][2], acc[mi][ni][3]);
            }
    } else {
#pragma unroll
        for (int mi = 0; mi < 4; mi++)
#pragma unroll
            for (int half = 0; half < 2; half++) {
                int mloc = byy * 128 + wm + mi * 16 + (lane >> 2) + half * 8;
                if (mloc >= CAPX) continue;
                float wgt = wout[e * CAPX + mloc];
                if (wgt == 0.f) continue;
                int tok = rout[e * CAPX + mloc];
                float* orow = out + (size_t)tok * 2048;
#pragma unroll
                for (int ni = 0; ni < 8; ni++) {
                    int cc = ncol0 + ni * 8;
                    atomicAdd(orow + cc,     wgt * acc[mi][ni][half * 2 + 0]);
                    atomicAdd(orow + cc + 1, wgt * acc[mi][ni][half * 2 + 1]);
                }
            }
    }
}

// ---------------- launch (three-stream fork/join; resources created ONCE) ----------------
extern "C" void kernel_launch(void* const* d_in, const int* in_sizes, int n_in,
                              void* d_out, int out_size) {
    const float* x   = (const float*)d_in[0];
    const float* gw  = (const float*)d_in[1];
    const float* eb  = (const float*)d_in[2];
    const float* sw1 = (const float*)d_in[3];
    const float* sw2 = (const float*)d_in[4];
    const float* rw1 = (const float*)d_in[5];
    const float* rw2 = (const float*)d_in[6];
    float* out = (float*)d_out;

    __half *Xr, *Hs, *sw1T, *sw2T, *rw1T, *rw2T;
    float *selw;
    int* seltok;
    cudaGetSymbolAddress((void**)&Xr, g_Xr);
    cudaGetSymbolAddress((void**)&Hs, g_Hs);
    cudaGetSymbolAddress((void**)&sw1T, g_sw1T);
    cudaGetSymbolAddress((void**)&sw2T, g_sw2T);
    cudaGetSymbolAddress((void**)&rw1T, g_rw1T);
    cudaGetSymbolAddress((void**)&rw2T, g_rw2T);
    cudaGetSymbolAddress((void**)&seltok, g_sel_tok);
    cudaGetSymbolAddress((void**)&selw, g_sel_w);

    // Streams/events created exactly once (first call = the uncaptured
    // correctness run). Capture and replay calls perform ZERO allocations, so
    // device free memory returns to the pre-capture baseline after teardown.
    static bool inited = false;
    static cudaStream_t s2, s3;
    static cudaEvent_t eFork, eG, eW1, eSel, eS2, eR2;
    if (!inited) {
        cudaStreamCreateWithFlags(&s2, cudaStreamNonBlocking);
        cudaStreamCreateWithFlags(&s3, cudaStreamNonBlocking);
        cudaEventCreateWithFlags(&eFork, cudaEventDisableTiming);
        cudaEventCreateWithFlags(&eG,    cudaEventDisableTiming);
        cudaEventCreateWithFlags(&eW1,   cudaEventDisableTiming);
        cudaEventCreateWithFlags(&eSel,  cudaEventDisableTiming);
        cudaEventCreateWithFlags(&eS2,   cudaEventDisableTiming);
        cudaEventCreateWithFlags(&eR2,   cudaEventDisableTiming);
        cudaFuncSetAttribute(gemm1_kernel<false>,
                             cudaFuncAttributeMaxDynamicSharedMemorySize, SMEM_BYTES);
        cudaFuncSetAttribute(gemm1_kernel<true>,
                             cudaFuncAttributeMaxDynamicSharedMemorySize, SMEM_BYTES);
        cudaFuncSetAttribute(gemm2_kernel<false>,
                             cudaFuncAttributeMaxDynamicSharedMemorySize, SMEM_BYTES);
        cudaFuncSetAttribute(gemm2_kernel<true>,
                             cudaFuncAttributeMaxDynamicSharedMemorySize, SMEM_BYTES);
        inited = true;
    }

    // fork s2, s3 from the (capturing) default stream
    cudaEventRecord(eFork, 0);
    cudaStreamWaitEvent(s2, eFork, 0);
    cudaStreamWaitEvent(s3, eFork, 0);

    // s2: sw1 transpose first (tiny — unblocks shared GEMM1 early), then the rest
    convT_one<<<dim3(2 * FF / 64, DD / 64), 256, 0, s2>>>(sw1, sw1T, DD, 2 * FF);
    cudaEventRecord(eW1, s2);
    convT_rest<<<dim3(32, 32, 15), 256, 0, s2>>>(rw1, sw2, rw2, rw1T, sw2T, rw2T);

    // s0: gating (+x->fp16)
    gating_kernel<<<TT, 256, 0, 0>>>(x, gw, eb);
    cudaEventRecord(eG, 0);

    // s3: selection (only routed chain needs it)
    cudaStreamWaitEvent(s3, eG, 0);
    select_kernel<<<EE, 1024, 0, s3>>>();
    cudaEventRecord(eSel, s3);

    // s0: shared chain (needs only sw1T + gating)
    cudaStreamWaitEvent(0, eW1, 0);
    gemm1_kernel<false><<<dim3(16, SH_TILES), 128, SMEM_BYTES, 0>>>(
        Xr, sw1T, Hs, nullptr);
    gemm2_kernel<false><<<dim3(16, SH_TILES), 128, SMEM_BYTES, 0>>>(
        Hs, sw2T, out, nullptr, nullptr);
    cudaEventRecord(eS2, 0);

    // s2: routed chain (weights in-order on s2; needs select)
    cudaStreamWaitEvent(s2, eSel, 0);
    gemm1_kernel<true><<<dim3(16, EE * RT_TILES), 128, SMEM_BYTES, s2>>>(
        Xr, rw1T, Hs, seltok);
    cudaStreamWaitEvent(s2, eS2, 0);      // routed scatter strictly after dense stores
    gemm2_kernel<true><<<dim3(16, EE * RT_TILES), 128, SMEM_BYTES, s2>>>(
        Hs, rw2T, out, seltok, selw);
    cudaEventRecord(eR2, s2);

    // join back to the origin stream
    cudaStreamWaitEvent(0, eR2, 0);
}